// round 17
// baseline (speedup 1.0000x reference)
#include <cuda_runtime.h>
#include <cuda_fp16.h>
#include <math.h>
#include <stdint.h>

// Problem constants
#define D_MODEL 1024
#define DW 512               // fp16x2 words per row
#define SEQ     2048
#define BATCH   2
#define HEADS   16
#define MTOT (BATCH * SEQ)   // 4096 rows
#define RPW (MTOT / 2)       // 2048 key-pair columns in g_Vp

// Scratch (device globals; no allocation allowed). Interior is fp16.
__device__ uint32_t g_Q[MTOT * DW];     // fp16 pairs, Q pre-scaled by 1/32
__device__ uint32_t g_K[MTOT * DW];
__device__ uint32_t g_Vp[D_MODEL * RPW]; // d-major paired-key: [d][rp] = (V[2rp][d],V[2rp+1][d])
__device__ uint32_t g_O[MTOT * DW];     // attention output, fp16 pairs
__device__ uint32_t g_Xq[MTOT * DW];    // fp16 copies of inputs
__device__ uint32_t g_Xk[MTOT * DW];
__device__ uint32_t g_Xv[MTOT * DW];
__device__ __half g_Wqt[D_MODEL * D_MODEL];   // fp16, TRANSPOSED [n][k]
__device__ __half g_Wkt[D_MODEL * D_MODEL];
__device__ __half g_Wvt[D_MODEL * D_MODEL];
__device__ __half g_Wot[D_MODEL * D_MODEL];

__device__ __forceinline__ uint32_t packh2(float lo, float hi) {
    __half2 h = __floats2half2_rn(lo, hi);
    return *reinterpret_cast<uint32_t*>(&h);
}

__device__ __forceinline__ void mma_f16(
    float& d0, float& d1, float& d2, float& d3,
    uint32_t a0, uint32_t a1, uint32_t a2, uint32_t a3,
    uint32_t b0, uint32_t b1)
{
    asm volatile(
        "mma.sync.aligned.m16n8k16.row.col.f32.f16.f16.f32 "
        "{%0,%1,%2,%3}, {%4,%5,%6,%7}, {%8,%9}, {%0,%1,%2,%3};\n"
        : "+f"(d0), "+f"(d1), "+f"(d2), "+f"(d3)
        : "r"(a0), "r"(a1), "r"(a2), "r"(a3), "r"(b0), "r"(b1));
}

__device__ __forceinline__ void ldsm4(
    uint32_t& r0, uint32_t& r1, uint32_t& r2, uint32_t& r3, uint32_t saddr)
{
    asm volatile(
        "ldmatrix.sync.aligned.m8n8.x4.shared.b16 {%0,%1,%2,%3}, [%4];"
        : "=r"(r0), "=r"(r1), "=r"(r2), "=r"(r3) : "r"(saddr));
}

__device__ __forceinline__ void cp16(uint32_t saddr, const void* g) {
    asm volatile("cp.async.cg.shared.global [%0], [%1], 16;\n"
                 :: "r"(saddr), "l"(g));
}
__device__ __forceinline__ void cp_commit() {
    asm volatile("cp.async.commit_group;\n");
}
template <int N>
__device__ __forceinline__ void cp_wait() {
    asm volatile("cp.async.wait_group %0;\n" :: "n"(N));
}

// ---------------------------------------------------------------------------
// Prep A: inputs -> fp16 pairs.
// ---------------------------------------------------------------------------
__global__ __launch_bounds__(256) void prep_in_kernel(
    const float* __restrict__ q, const float* __restrict__ k,
    const float* __restrict__ v)
{
    const int z = blockIdx.y;
    const float* src = (z == 0) ? q : (z == 1) ? k : v;
    uint32_t* dst = (z == 0) ? g_Xq : (z == 1) ? g_Xk : g_Xv;
    const int i = blockIdx.x * 256 + threadIdx.x;   // uint4 index
    const float4 f0 = reinterpret_cast<const float4*>(src)[i * 2];
    const float4 f1 = reinterpret_cast<const float4*>(src)[i * 2 + 1];
    uint4 u;
    u.x = packh2(f0.x, f0.y); u.y = packh2(f0.z, f0.w);
    u.z = packh2(f1.x, f1.y); u.w = packh2(f1.z, f1.w);
    reinterpret_cast<uint4*>(dst)[i] = u;
}

// ---------------------------------------------------------------------------
// Prep B: weights -> fp16 TRANSPOSED: Wt[n][k] = W[k][n].
// ---------------------------------------------------------------------------
__global__ __launch_bounds__(256) void prep_wt_kernel(
    const float* __restrict__ Wq, const float* __restrict__ Wk,
    const float* __restrict__ Wv, const float* __restrict__ Wo)
{
    __shared__ float tile[32][33];
    const int z = blockIdx.z;
    const float* src = (z == 0) ? Wq : (z == 1) ? Wk : (z == 2) ? Wv : Wo;
    __half* dst = (z == 0) ? g_Wqt : (z == 1) ? g_Wkt : (z == 2) ? g_Wvt : g_Wot;
    const int tx = threadIdx.x & 31;
    const int ty = threadIdx.x >> 5;
    const int n0 = blockIdx.x * 32;
    const int k0 = blockIdx.y * 32;
#pragma unroll
    for (int j = 0; j < 32; j += 8)
        tile[ty + j][tx] = src[(size_t)(k0 + ty + j) * D_MODEL + n0 + tx];
    __syncthreads();
#pragma unroll
    for (int j = 0; j < 32; j += 8)
        dst[(size_t)(n0 + ty + j) * D_MODEL + k0 + tx] =
            __float2half_rn(tile[tx][ty + j]);
}

// ---------------------------------------------------------------------------
// fp16 GEMM with ldmatrix.x4 fragment loads (R16, proven). MODE: 0 fp16-pair
// out, 1 V d-major paired-key out, 2 fp32 out.
// ---------------------------------------------------------------------------
#define GST 36
#define G_AW (128 * GST)
#define G_STAGE (2 * G_AW)
#define GEMM_SMEM (3 * G_STAGE * 4)     // 110592 bytes
#define GNT (D_MODEL / 64)              // 16 k-tiles

template <int MODE>
__device__ __forceinline__ void gemm_body(
    const uint32_t* __restrict__ A, const __half* __restrict__ Wt,
    const float* __restrict__ bias, void* Cout, float outScale)
{
    extern __shared__ uint32_t gsm[];
    const uint32_t su = (uint32_t)__cvta_generic_to_shared(gsm);

    const int tid  = threadIdx.x;
    const int warp = tid >> 5;
    const int lane = tid & 31;
    const int wm = (warp & 1) * 64;
    const int wn = (warp >> 1) * 32;
    const int rowBlk = blockIdx.y * 128;
    const int colBlk = blockIdx.x * 128;
    const int lr = lane >> 2;
    const int lc = lane & 3;
    const int m4 = lane >> 3;
    const int r8 = lane & 7;

    auto issue = [&](int t, int s) {
        const uint32_t abase = su + (uint32_t)(s * G_STAGE) * 4;
        const uint32_t bbase = abase + (uint32_t)G_AW * 4;
#pragma unroll
        for (int i = 0; i < 4; i++) {
            const int idx = tid + 256 * i;
            const int r = idx >> 3;
            const int c = idx & 7;
            cp16(abase + (uint32_t)(r * GST + c * 4) * 4,
                 &A[(size_t)(rowBlk + r) * DW + t * 32 + c * 4]);
        }
#pragma unroll
        for (int i = 0; i < 4; i++) {
            const int idx = tid + 256 * i;
            const int r = idx >> 3;
            const int c = idx & 7;
            cp16(bbase + (uint32_t)(r * GST + c * 4) * 4,
                 &Wt[(size_t)(colBlk + r) * D_MODEL + t * 64 + c * 8]);
        }
        cp_commit();
    };

    float acc[4][4][4];
#pragma unroll
    for (int mi = 0; mi < 4; mi++)
#pragma unroll
        for (int ni = 0; ni < 4; ni++)
#pragma unroll
            for (int r = 0; r < 4; r++) acc[mi][ni][r] = 0.0f;

    issue(0, 0);
    issue(1, 1);

    for (int t = 0; t < GNT; t++) {
        if (t + 1 < GNT) cp_wait<1>(); else cp_wait<0>();
        __syncthreads();
        if (t + 2 < GNT) issue(t + 2, (t + 2) % 3);

        const uint32_t abase = su + (uint32_t)((t % 3) * G_STAGE) * 4;
        const uint32_t bbase = abase + (uint32_t)G_AW * 4;

#pragma unroll
        for (int ss = 0; ss < 4; ss++) {
            const int k0 = ss * 8;
            uint32_t af[4][4];
#pragma unroll
            for (int mi = 0; mi < 4; mi++) {
                const int row = wm + mi * 16 + (m4 & 1) * 8 + r8;
                const int word = k0 + (m4 >> 1) * 4;
                ldsm4(af[mi][0], af[mi][1], af[mi][2], af[mi][3],
                      abase + (uint32_t)(row * GST + word) * 4);
            }
            uint32_t bf[4][2];
#pragma unroll
            for (int nip = 0; nip < 2; nip++) {
                const int n = wn + (nip * 2 + (m4 >> 1)) * 8 + r8;
                const int word = k0 + (m4 & 1) * 4;
                ldsm4(bf[nip * 2][0], bf[nip * 2][1],
                      bf[nip * 2 + 1][0], bf[nip * 2 + 1][1],
                      bbase + (uint32_t)(n * GST + word) * 4);
            }
#pragma unroll
            for (int mi = 0; mi < 4; mi++)
#pragma unroll
                for (int ni = 0; ni < 4; ni++)
                    mma_f16(acc[mi][ni][0], acc[mi][ni][1],
                            acc[mi][ni][2], acc[mi][ni][3],
                            af[mi][0], af[mi][1], af[mi][2], af[mi][3],
                            bf[ni][0], bf[ni][1]);
        }
    }

#pragma unroll
    for (int mi = 0; mi < 4; mi++) {
        const int r0 = rowBlk + wm + mi * 16 + lr;
#pragma unroll
        for (int ni = 0; ni < 4; ni++) {
            const int c0 = colBlk + wn + ni * 8 + lc * 2;
            const float2 bb = *reinterpret_cast<const float2*>(&bias[c0]);
            const float v00 = (acc[mi][ni][0] + bb.x) * outScale;
            const float v01 = (acc[mi][ni][1] + bb.y) * outScale;
            const float v10 = (acc[mi][ni][2] + bb.x) * outScale;
            const float v11 = (acc[mi][ni][3] + bb.y) * outScale;
            if (MODE == 0) {
                uint32_t* C = (uint32_t*)Cout;
                C[(size_t)r0 * DW + c0 / 2] = packh2(v00, v01);
                C[(size_t)(r0 + 8) * DW + c0 / 2] = packh2(v10, v11);
            } else if (MODE == 2) {
                float* C = (float*)Cout;
                float2 o0, o1;
                o0.x = v00; o0.y = v01;
                o1.x = v10; o1.y = v11;
                *reinterpret_cast<float2*>(&C[(size_t)r0 * D_MODEL + c0]) = o0;
                *reinterpret_cast<float2*>(&C[(size_t)(r0 + 8) * D_MODEL + c0]) = o1;
            } else {
                uint32_t* Vp = (uint32_t*)Cout;
                const float x00 = __shfl_xor_sync(0xffffffffu, v00, 4);
                const float x01 = __shfl_xor_sync(0xffffffffu, v01, 4);
                const float x10 = __shfl_xor_sync(0xffffffffu, v10, 4);
                const float x11 = __shfl_xor_sync(0xffffffffu, v11, 4);
                if ((lr & 1) == 0) {
                    const size_t rp = (size_t)(r0 >> 1);
                    Vp[(size_t)c0 * RPW + rp]       = packh2(v00, x00);
                    Vp[(size_t)(c0 + 1) * RPW + rp] = packh2(v01, x01);
                } else {
                    const size_t rp = (size_t)((r0 + 7) >> 1);
                    Vp[(size_t)c0 * RPW + rp]       = packh2(x10, v10);
                    Vp[(size_t)(c0 + 1) * RPW + rp] = packh2(x11, v11);
                }
            }
        }
    }
}

__global__ __launch_bounds__(256, 2) void qkv_gemm_kernel(
    const float* __restrict__ bq, const float* __restrict__ bk,
    const float* __restrict__ bv)
{
    const int z = blockIdx.z;
    if (z == 0)      gemm_body<0>(g_Xq, g_Wqt, bq, g_Q, 0.03125f);
    else if (z == 1) gemm_body<0>(g_Xk, g_Wkt, bk, g_K, 1.0f);
    else             gemm_body<1>(g_Xv, g_Wvt, bv, g_Vp, 1.0f);
}

__global__ __launch_bounds__(256, 2) void gemm_o_kernel(
    const float* __restrict__ bias, float* __restrict__ C)
{
    gemm_body<2>(g_O, g_Wot, bias, C, 1.0f);
}

// ---------------------------------------------------------------------------
// fp16 flash attention: KCH=128 (16 chunks, half the barriers), S(j)/O(j)
// interleaved per 16-key block (only one pf[4] live; O-mma(j) overlaps
// S-mma(j+1)). Key/mma/l-accumulation order identical to R16 ->
// bit-identical numerics expected.
// K smem [key 0..127][36]; V smem [d 0..63][68] (64 kp words + pad).
// ---------------------------------------------------------------------------
#define AKST 36
#define AVST 68
#define A_QW (128 * AKST)     // 4608 (Q staging)
#define A_KW (128 * AKST)     // 4608 per K buffer
#define A_VW (64 * AVST)      // 4352 per V buffer
#define OFFK A_QW
#define OFFV (A_QW + 2 * A_KW)
#define ATTN_SMEM ((OFFV + 2 * A_VW) * 4)   // (4608+9216+8704)*4 = 90112 B
#define NTC (SEQ / 128)                      // 16 chunks

__global__ __launch_bounds__(256, 2) void attn_kernel()
{
    extern __shared__ uint32_t smu[];
    const uint32_t su = (uint32_t)__cvta_generic_to_shared(smu);
    uint32_t* Qsm = smu;

    const int tid  = threadIdx.x;
    const int warp = tid >> 5;
    const int lane = tid & 31;
    const int lr = lane >> 2;
    const int lc = lane & 3;
    const int wm = warp * 16;

    const int qblk = blockIdx.x;
    const int bh   = blockIdx.y;
    const int b = bh >> 4;
    const int h = bh & 15;
    const size_t baseRow = (size_t)b * SEQ;
    const size_t baseRp  = (size_t)b * (SEQ / 2);

    auto issue_chunk = [&](int kt, int buf) {
        const uint32_t kb = su + (uint32_t)(OFFK + buf * A_KW) * 4;
        const uint32_t vb = su + (uint32_t)(OFFV + buf * A_VW) * 4;
        // K: 128 keys x 32 words = 4096 words -> 4 cp16/thread
#pragma unroll
        for (int i = 0; i < 4; i++) {
            const int idx = tid + 256 * i;
            const int r = idx >> 3;          // 0..127 (key)
            const int c = idx & 7;
            cp16(kb + (uint32_t)(r * AKST + c * 4) * 4,
                 &g_K[(baseRow + (size_t)kt * 128 + r) * DW + h * 32 + c * 4]);
        }
        // V: 64 d-rows x 64 kp words = 4096 words -> 4 cp16/thread
#pragma unroll
        for (int i = 0; i < 4; i++) {
            const int idx = tid + 256 * i;
            const int r = idx >> 4;          // 0..63 (dim d)
            const int c = idx & 15;          // 16B chunk among 64 kp words
            cp16(vb + (uint32_t)(r * AVST + c * 4) * 4,
                 &g_Vp[(size_t)(h * 64 + r) * RPW + baseRp + kt * 64 + c * 4]);
        }
        cp_commit();
    };

    issue_chunk(0, 0);

    // stage Q (fp16 words, already scaled)
#pragma unroll
    for (int i = 0; i < 4; i++) {
        const int idx = tid + 256 * i;
        const int r  = idx >> 3;
        const int c4 = (idx & 7) * 4;
        *reinterpret_cast<uint4*>(&Qsm[r * AKST + c4]) =
            *reinterpret_cast<const uint4*>(
                &g_Q[(baseRow + (size_t)qblk * 128 + r) * DW + h * 32 + c4]);
    }
    __syncthreads();

    uint32_t qf[4][4];
#pragma unroll
    for (int ks = 0; ks < 4; ks++) {
        const int k0 = ks * 8;
        qf[ks][0] = Qsm[(wm + lr    ) * AKST + k0 + lc    ];
        qf[ks][1] = Qsm[(wm + lr + 8) * AKST + k0 + lc    ];
        qf[ks][2] = Qsm[(wm + lr    ) * AKST + k0 + lc + 4];
        qf[ks][3] = Qsm[(wm + lr + 8) * AKST + k0 + lc + 4];
    }

    const int m4 = lane >> 3;
    const int r8 = lane & 7;

    float oacc[8][4];
#pragma unroll
    for (int ni = 0; ni < 8; ni++)
#pragma unroll
        for (int r = 0; r < 4; r++) oacc[ni][r] = 0.0f;
    float l0 = 0.0f, l1 = 0.0f;

    for (int kt = 0; kt < NTC; kt++) {
        const int buf = kt & 1;
        cp_wait<0>();
        __syncthreads();
        if (kt + 1 < NTC) issue_chunk(kt + 1, buf ^ 1);

        const uint32_t kbase = su + (uint32_t)(OFFK + buf * A_KW) * 4;
        const uint32_t vbase = su + (uint32_t)(OFFV + buf * A_VW) * 4;

        // ---- per 16-key block j: S -> exp -> pf -> O (interleaved) ----
#pragma unroll
        for (int j = 0; j < 8; j++) {
            float s2[2][4];
#pragma unroll
            for (int t = 0; t < 2; t++)
#pragma unroll
                for (int r = 0; r < 4; r++) s2[t][r] = 0.0f;
#pragma unroll
            for (int ks = 0; ks < 4; ks++) {
                const int key  = (j * 2 + (m4 >> 1)) * 8 + r8;   // 0..127
                const int word = ks * 8 + (m4 & 1) * 4;
                uint32_t kb0, kb1, kb2, kb3;
                ldsm4(kb0, kb1, kb2, kb3,
                      kbase + (uint32_t)(key * AKST + word) * 4);
                mma_f16(s2[0][0], s2[0][1], s2[0][2], s2[0][3],
                        qf[ks][0], qf[ks][1], qf[ks][2], qf[ks][3], kb0, kb1);
                mma_f16(s2[1][0], s2[1][1], s2[1][2], s2[1][3],
                        qf[ks][0], qf[ks][1], qf[ks][2], qf[ks][3], kb2, kb3);
            }
            uint32_t pf[4];
#pragma unroll
            for (int t = 0; t < 2; t++) {
                const float p0 = __expf(s2[t][0]);
                const float p1 = __expf(s2[t][1]);
                const float p2 = __expf(s2[t][2]);
                const float p3 = __expf(s2[t][3]);
                l0 += p0 + p1;
                l1 += p2 + p3;
                pf[t * 2 + 0] = packh2(p0, p1);
                pf[t * 2 + 1] = packh2(p2, p3);
            }
            // O += P_j @ V_j  (k-block j of the 128-key chunk)
#pragma unroll
            for (int nip = 0; nip < 4; nip++) {
                const int d    = (nip * 2 + (m4 >> 1)) * 8 + r8;
                const int word = j * 8 + (m4 & 1) * 4;
                uint32_t vb0, vb1, vb2, vb3;
                ldsm4(vb0, vb1, vb2, vb3,
                      vbase + (uint32_t)(d * AVST + word) * 4);
                mma_f16(oacc[nip * 2][0], oacc[nip * 2][1],
                        oacc[nip * 2][2], oacc[nip * 2][3],
                        pf[0], pf[1], pf[2], pf[3], vb0, vb1);
                mma_f16(oacc[nip * 2 + 1][0], oacc[nip * 2 + 1][1],
                        oacc[nip * 2 + 1][2], oacc[nip * 2 + 1][3],
                        pf[0], pf[1], pf[2], pf[3], vb2, vb3);
            }
        }
        // next iteration's barrier (after cp_wait) orders these reads
        // before buf is overwritten.
    }

    // ---- final row-sum reduction, normalize, store fp16 pairs ----
    l0 += __shfl_xor_sync(0xffffffffu, l0, 1);
    l0 += __shfl_xor_sync(0xffffffffu, l0, 2);
    l1 += __shfl_xor_sync(0xffffffffu, l1, 1);
    l1 += __shfl_xor_sync(0xffffffffu, l1, 2);
    const float inv0 = 1.0f / l0;
    const float inv1 = 1.0f / l1;
    const size_t r0 = baseRow + (size_t)qblk * 128 + wm + lr;
#pragma unroll
    for (int ni = 0; ni < 8; ni++) {
        const int cw = h * 32 + ni * 4 + lc;
        g_O[r0 * DW + cw] = packh2(oacc[ni][0] * inv0, oacc[ni][1] * inv0);
        g_O[(r0 + 8) * DW + cw] = packh2(oacc[ni][2] * inv1, oacc[ni][3] * inv1);
    }
}

// ---------------------------------------------------------------------------
extern "C" void kernel_launch(void* const* d_in, const int* in_sizes, int n_in,
                              void* d_out, int out_size)
{
    const float* queries = (const float*)d_in[0];
    const float* keys    = (const float*)d_in[1];
    const float* values  = (const float*)d_in[2];
    const float* Wq = (const float*)d_in[3];
    const float* bq = (const float*)d_in[4];
    const float* Wk = (const float*)d_in[5];
    const float* bk = (const float*)d_in[6];
    const float* Wv = (const float*)d_in[7];
    const float* bv = (const float*)d_in[8];
    const float* Wo = (const float*)d_in[9];
    const float* bo = (const float*)d_in[10];
    float* out = (float*)d_out;

    prep_in_kernel<<<dim3(MTOT * DW / 4 / 256, 3), 256>>>(queries, keys, values);
    prep_wt_kernel<<<dim3(32, 32, 4), 256>>>(Wq, Wk, Wv, Wo);

    cudaFuncSetAttribute(qkv_gemm_kernel,
                         cudaFuncAttributeMaxDynamicSharedMemorySize, GEMM_SMEM);
    cudaFuncSetAttribute(gemm_o_kernel,
                         cudaFuncAttributeMaxDynamicSharedMemorySize, GEMM_SMEM);
    cudaFuncSetAttribute(attn_kernel,
                         cudaFuncAttributeMaxDynamicSharedMemorySize, ATTN_SMEM);

    qkv_gemm_kernel<<<dim3(8, 32, 3), 256, GEMM_SMEM>>>(bq, bk, bv);

    attn_kernel<<<dim3(SEQ / 128, BATCH * HEADS), 256, ATTN_SMEM>>>();

    gemm_o_kernel<<<dim3(8, 32), 256, GEMM_SMEM>>>(bo, out);
}